// round 11
// baseline (speedup 1.0000x reference)
#include <cuda_runtime.h>

// Problem constants (fixed by setup_inputs):
// B=16, C=1, H=W=128, WS=8, N = B*WS*WS = 1024 windows, mask all ones.
// Canvas per batch: 1024 x 1024. Output = [canvas (16.7M f32) | windows copy (16.7M f32)].

#define NW        1024            // number of windows
#define BATCH     16
#define WSZ       8
#define CELLS     (WSZ * WSZ)     // 64 cells per batch
#define NTILES    (BATCH * CELLS) // 1024
#define HH        128
#define TILE_F4   (HH * HH / 4)   // 4096 float4 per tile
#define CANV_ROW4 (1024 / 4)      // 256 float4 per canvas row
#define CANV_B4   (1024 * 1024 / 4)

#define NSEG      4               // segments per tile
#define SEG_F4    (TILE_F4 / NSEG)      // 1024 float4 per segment
#define GTHREADS  256
#define JPT       (SEG_F4 / GTHREADS)   // 4 float4 per thread

// ---------------------------------------------------------------------------
// Single fused kernel: grid (NSEG, NTILES) x 256 threads, seg-major so the 4
// CTAs of one tile sweep each window / the canvas tile contiguously.
//
// Low-latency prologue (the R10 bottleneck): the mask->csum reduction and the
// positions read are issued CONCURRENTLY --
//   * every thread preloads positions of its 4 windows (2x int4) immediately;
//   * warp 0 (lanes 0-15) sums one mask row each (16 independent int4 loads)
//     and produces the inclusive csum with a shfl scan -- no shared atomics,
//     no intermediate barriers.
// Only 2 block-wide syncs remain: csum-publish and list-complete.
// Classification (searchsorted over 16 smem entries + position compare) is
// pure ALU on registers.
//
// Then gather the k matching windows over this block's 1024-float4 segment
// with 4 independent streaming loads in flight per thread, fusing the
// verbatim windows copy (each window byte read exactly once chip-wide), and
// write the normalized canvas segment. Loads read-once -> __ldcs; stores
// default write-back so L2 absorbs write bursts.
// ---------------------------------------------------------------------------
__global__ void __launch_bounds__(GTHREADS) hre_fused_kernel(
    const float4* __restrict__ win4,      // windows as float4
    const int4*   __restrict__ pos4,      // positions as int4: [NW*2/4]
    const int4*   __restrict__ mask4,     // mask as int4: [BATCH*CELLS/4]
    float4* __restrict__ canvas4,         // output canvas (first half)
    float4* __restrict__ copy4)           // output windows copy (second half)
{
    const int seg  = blockIdx.x;          // seg-major: consecutive bids share a tile
    const int tile = blockIdx.y;
    const int tid  = threadIdx.x;
    const int lane = tid & 31;

    const int b    = tile >> 6;           // batch of this tile
    const int cell = tile & 63;
    const int ty   = cell >> 3;
    const int tx   = cell & 7;

    __shared__ int csum_s[BATCH];
    __shared__ int list_cnt;
    __shared__ unsigned short list[CELLS];

    // --- speculative positions preload: windows [tid*4, tid*4+4) ----------
    // pos layout: [NW,2] ints -> int4 covers 2 windows. tid*2, tid*2+1.
    const int4 pA = pos4[tid * 2 + 0];    // win tid*4+0: (x=py,y=px), +1: (z,w)
    const int4 pB = pos4[tid * 2 + 1];    // win tid*4+2, tid*4+3

    if (tid == 0) list_cnt = 0;

    // --- warp 0: per-batch mask sums + shfl inclusive scan -----------------
    if (tid < 32) {
        int s = 0;
        if (lane < BATCH) {
            #pragma unroll
            for (int j = 0; j < CELLS / 4; ++j) {       // 16 int4 loads
                const int4 m = mask4[lane * (CELLS / 4) + j];
                s += m.x + m.y + m.z + m.w;
            }
        }
        // inclusive scan over lanes 0..15 (lanes 16-31 carry garbage, unused)
        #pragma unroll
        for (int off = 1; off < BATCH; off <<= 1) {
            const int n = __shfl_up_sync(0xffffffffu, s, off);
            if (lane >= off) s += n;
        }
        if (lane < BATCH) csum_s[lane] = s;
    }
    __syncthreads();                       // csum published (sync #1)

    // --- classify my 4 windows (registers + smem csum, pure ALU) -----------
    {
        int py[4], px[4];
        py[0] = pA.x; px[0] = pA.y;  py[1] = pA.z; px[1] = pA.w;
        py[2] = pB.x; px[2] = pB.y;  py[3] = pB.z; px[3] = pB.w;
        #pragma unroll
        for (int j = 0; j < 4; ++j) {
            const int i = tid * 4 + j;
            if (py[j] == ty && px[j] == tx) {
                int bb = 0;                               // searchsorted right
                while (bb < BATCH - 1 && i >= csum_s[bb]) ++bb;
                if (bb == b) {
                    const int s = atomicAdd(&list_cnt, 1);
                    list[s] = (unsigned short)i;
                }
            }
        }
    }
    __syncthreads();                       // list complete (sync #2)
    const int k = list_cnt;

    // --- gather + fused copy ------------------------------------------------
    const int p0 = seg * SEG_F4 + tid;    // first float4 owned by this thread

    float4 acc[JPT];
    #pragma unroll
    for (int j = 0; j < JPT; ++j)
        acc[j] = make_float4(0.f, 0.f, 0.f, 0.f);

    for (int w = 0; w < k; ++w) {
        const int wi = list[w];
        const float4* __restrict__ src = win4  + (size_t)wi * TILE_F4 + p0;
        float4*       __restrict__ dst = copy4 + (size_t)wi * TILE_F4 + p0;

        float4 v[JPT];
        #pragma unroll
        for (int j = 0; j < JPT; ++j)     // 4 independent streaming loads
            v[j] = __ldcs(src + j * GTHREADS);
        #pragma unroll
        for (int j = 0; j < JPT; ++j) {
            dst[j * GTHREADS] = v[j];     // fused windows passthrough (write-back)
            acc[j].x += v[j].x; acc[j].y += v[j].y;
            acc[j].z += v[j].z; acc[j].w += v[j].w;
        }
    }

    // --- normalized canvas writes ------------------------------------------
    const float inv = 1.0f / ((float)k + 1e-6f);
    const int cbase = b * CANV_B4 + ty * HH * CANV_ROW4 + tx * (HH / 4);

    #pragma unroll
    for (int j = 0; j < JPT; ++j) {
        const int p4 = p0 + j * GTHREADS;       // 0..4095 within tile
        const int r  = p4 >> 5;                 // 32 f4 per tile row
        const int c4 = p4 & 31;
        canvas4[cbase + r * CANV_ROW4 + c4] =
            make_float4(acc[j].x * inv, acc[j].y * inv,
                        acc[j].z * inv, acc[j].w * inv);
    }
}

// ---------------------------------------------------------------------------
extern "C" void kernel_launch(void* const* d_in, const int* in_sizes, int n_in,
                              void* d_out, int out_size)
{
    const float* windows   = (const float*)d_in[0];   // [NW,1,128,128] f32
    const int*   positions = (const int*)  d_in[1];   // [NW,2] i32
    const int*   mask      = (const int*)  d_in[2];   // [16,64] i32
    (void)in_sizes; (void)n_in; (void)out_size;

    float* out = (float*)d_out;
    float4* canvas4 = (float4*)out;
    float4* copy4   = (float4*)(out + (size_t)BATCH * 1024 * 1024);

    dim3 grid(NSEG, NTILES);              // seg-major
    hre_fused_kernel<<<grid, GTHREADS>>>((const float4*)windows,
                                         (const int4*)positions,
                                         (const int4*)mask,
                                         canvas4, copy4);
}

// round 13
// speedup vs baseline: 1.0534x; 1.0534x over previous
#include <cuda_runtime.h>

// Problem constants (fixed by setup_inputs):
// B=16, C=1, H=W=128, WS=8, N = B*WS*WS = 1024 windows, mask all ones.
// Canvas per batch: 1024 x 1024. Output = [canvas (16.7M f32) | windows copy (16.7M f32)].

#define NW        1024            // number of windows
#define BATCH     16
#define WSZ       8
#define CELLS     (WSZ * WSZ)     // 64 cells per batch
#define NTILES    (BATCH * CELLS) // 1024
#define HH        128
#define TILE_F4   (HH * HH / 4)   // 4096 float4 per tile
#define CANV_ROW4 (1024 / 4)      // 256 float4 per canvas row
#define CANV_B4   (1024 * 1024 / 4)

#define NSEG      4               // segments per tile
#define SEG_F4    (TILE_F4 / NSEG)      // 1024 float4 per segment
#define GTHREADS  256
#define JPT       (SEG_F4 / GTHREADS)   // 4 float4 per thread

// ---------------------------------------------------------------------------
// Single fused kernel: grid (NSEG, NTILES) x 256 threads, seg-major so the 4
// CTAs of one tile sweep each window / the canvas tile contiguously.
//
// Low-latency prologue (single L2 round-trip on the critical path):
//   * warp 0: per-batch mask row sums (16 lanes x 16 independent int4 loads)
//     + shfl inclusive scan -> csum in smem.
//   * warp 1 (CONCURRENTLY): speculative load of positions for the contiguous
//     window range [b*64, (b+1)*64) into smem (32 int4 = 1 KB, one warp only).
//   * one barrier; if csum confirms the speculation (true for the all-ones
//     mask: csum[b-1]==64b && csum[b]==64(b+1)), classify from smem with pure
//     ALU. Otherwise fall back to a generic gmem scan of [csum[b-1],csum[b])
//     (correct for arbitrary masks, just slower and never taken here).
//   * second barrier publishes the list.
//
// Data phase (unchanged from the best config): gather the k matching windows
// over this block's 1024-float4 segment with 4 independent streaming loads in
// flight per thread, fusing the verbatim windows copy (each window byte read
// exactly once chip-wide), then write the normalized canvas segment.
// Loads read-once -> __ldcs; stores default write-back so L2 absorbs bursts.
// ---------------------------------------------------------------------------
__global__ void __launch_bounds__(GTHREADS) hre_fused_kernel(
    const float4* __restrict__ win4,      // windows as float4
    const int*    __restrict__ positions, // [NW,2] i32
    const int4*   __restrict__ mask4,     // mask as int4: [BATCH*CELLS/4]
    float4* __restrict__ canvas4,         // output canvas (first half)
    float4* __restrict__ copy4)           // output windows copy (second half)
{
    const int seg  = blockIdx.x;          // seg-major: consecutive bids share a tile
    const int tile = blockIdx.y;
    const int tid  = threadIdx.x;
    const int lane = tid & 31;

    const int b    = tile >> 6;           // batch of this tile
    const int cell = tile & 63;
    const int ty   = cell >> 3;
    const int tx   = cell & 7;

    __shared__ int csum_s[BATCH];
    __shared__ int pos_s[CELLS * 2];      // speculative positions of batch b
    __shared__ int list_cnt;
    __shared__ unsigned short list[CELLS];

    if (tid == 64) list_cnt = 0;

    // --- warp 0: mask row sums + shfl inclusive scan ------------------------
    if (tid < 32) {
        int s = 0;
        if (lane < BATCH) {
            #pragma unroll
            for (int j = 0; j < CELLS / 4; ++j) {        // 16 independent int4
                const int4 m = mask4[lane * (CELLS / 4) + j];
                s += m.x + m.y + m.z + m.w;
            }
        }
        #pragma unroll
        for (int off = 1; off < BATCH; off <<= 1) {      // inclusive scan 0..15
            const int n = __shfl_up_sync(0xffffffffu, s, off);
            if (lane >= off) s += n;
        }
        if (lane < BATCH) csum_s[lane] = s;
    }
    // --- warp 1 (concurrent): speculative positions [b*64, b*64+64) ---------
    else if (tid < 64) {
        const int4 p = ((const int4*)positions)[b * (CELLS / 2) + lane];
        ((int4*)pos_s)[lane] = p;
    }
    __syncthreads();                       // csum + speculative positions ready

    const int win_start = (b == 0) ? 0 : csum_s[b - 1];
    const int win_end   = csum_s[b];
    const bool fast = (win_start == b * CELLS) && (win_end == (b + 1) * CELLS);

    if (fast) {
        // classify from smem: thread w < 64 checks local window w
        if (tid < CELLS) {
            const int py = pos_s[2 * tid + 0];
            const int px = pos_s[2 * tid + 1];
            if (py == ty && px == tx) {
                const int s = atomicAdd(&list_cnt, 1);
                list[s] = (unsigned short)(b * CELLS + tid);
            }
        }
    } else {
        // generic fallback: scan this batch's range from gmem
        for (int i = win_start + tid; i < win_end; i += GTHREADS) {
            const int py = positions[2 * i + 0];
            const int px = positions[2 * i + 1];
            if (py == ty && px == tx) {
                const int s = atomicAdd(&list_cnt, 1);
                list[s] = (unsigned short)i;
            }
        }
    }
    __syncthreads();                       // list complete
    const int k = list_cnt;

    // --- gather + fused copy ------------------------------------------------
    const int p0 = seg * SEG_F4 + tid;    // first float4 owned by this thread

    float4 acc[JPT];
    #pragma unroll
    for (int j = 0; j < JPT; ++j)
        acc[j] = make_float4(0.f, 0.f, 0.f, 0.f);

    for (int w = 0; w < k; ++w) {
        const int wi = list[w];
        const float4* __restrict__ src = win4  + (size_t)wi * TILE_F4 + p0;
        float4*       __restrict__ dst = copy4 + (size_t)wi * TILE_F4 + p0;

        float4 v[JPT];
        #pragma unroll
        for (int j = 0; j < JPT; ++j)     // 4 independent streaming loads
            v[j] = __ldcs(src + j * GTHREADS);
        #pragma unroll
        for (int j = 0; j < JPT; ++j) {
            dst[j * GTHREADS] = v[j];     // fused windows passthrough (write-back)
            acc[j].x += v[j].x; acc[j].y += v[j].y;
            acc[j].z += v[j].z; acc[j].w += v[j].w;
        }
    }

    // --- normalized canvas writes ------------------------------------------
    const float inv = 1.0f / ((float)k + 1e-6f);
    const int cbase = b * CANV_B4 + ty * HH * CANV_ROW4 + tx * (HH / 4);

    #pragma unroll
    for (int j = 0; j < JPT; ++j) {
        const int p4 = p0 + j * GTHREADS;       // 0..4095 within tile
        const int r  = p4 >> 5;                 // 32 f4 per tile row
        const int c4 = p4 & 31;
        canvas4[cbase + r * CANV_ROW4 + c4] =
            make_float4(acc[j].x * inv, acc[j].y * inv,
                        acc[j].z * inv, acc[j].w * inv);
    }
}

// ---------------------------------------------------------------------------
extern "C" void kernel_launch(void* const* d_in, const int* in_sizes, int n_in,
                              void* d_out, int out_size)
{
    const float* windows   = (const float*)d_in[0];   // [NW,1,128,128] f32
    const int*   positions = (const int*)  d_in[1];   // [NW,2] i32
    const int*   mask      = (const int*)  d_in[2];   // [16,64] i32
    (void)in_sizes; (void)n_in; (void)out_size;

    float* out = (float*)d_out;
    float4* canvas4 = (float4*)out;
    float4* copy4   = (float4*)(out + (size_t)BATCH * 1024 * 1024);

    dim3 grid(NSEG, NTILES);              // seg-major
    hre_fused_kernel<<<grid, GTHREADS>>>((const float4*)windows,
                                         positions,
                                         (const int4*)mask,
                                         canvas4, copy4);
}